// round 10
// baseline (speedup 1.0000x reference)
#include <cuda_runtime.h>
#include <cuda_bf16.h>
#include <cstdint>

// Problem constants
constexpr int B_   = 4;
constexpr int M_   = 65536;
constexpr int N_   = 16384;
constexpr int CPRE = 64;
constexpr int CCUR = 128;
constexpr int CIN  = 192;
constexpr int DOUT = 128;

constexpr int MT      = 128;
constexpr int THREADS = 512;   // 16 warps -> 4 per SMSP

// SMEM layouts (bf16 element strides; word stride ≡ 4 mod 8 -> conflict-free LDSM;
// all row starts 16B-aligned for cp.async)
constexpr int SXA = 136;   // pre_x tile, k-major: [64 k][128 m + pad]
constexpr int SXG = 136;   // gather tile, m-major: [128 m][128 k' + pad]
constexpr int SW  = 200;   // w tile, d-major: [128 d][192 k + pad]

constexpr int SM_IDX = 0;                       // 128 int
constexpr int SM_SC  = 512;                     // 128 f
constexpr int SM_BI  = 1024;                    // 128 f
constexpr int SM_XAH = 2048;
constexpr int SM_XAL = SM_XAH + 64 * SXA * 2;
constexpr int SM_XGH = SM_XAL + 64 * SXA * 2;
constexpr int SM_XGL = SM_XGH + 128 * SXG * 2;
constexpr int SM_WH  = SM_XGL + 128 * SXG * 2;
constexpr int SM_WL  = SM_WH + 128 * SW * 2;
constexpr int SM_TOT = SM_WL + 128 * SW * 2;    // 208896 (~204 KB)

// Pre-split scratch: ONLY data with cross-block reuse (cur_x ~16x, W 2048x).
__device__ uint16_t g_curT_h[(size_t)B_ * N_ * CCUR];   // (B,N,C) 16 MiB
__device__ uint16_t g_curT_l[(size_t)B_ * N_ * CCUR];
__device__ uint32_t g_wh[128 * (SW / 2)];               // W hi smem image [d][k/2]
__device__ uint32_t g_wl[128 * (SW / 2)];

// ---------------------------------------------------------------------------
__device__ __forceinline__ uint32_t pk2(float a, float b) {
    __nv_bfloat162 t = __floats2bfloat162_rn(a, b);
    return *(uint32_t*)&t;
}
__device__ __forceinline__ void split2(float a, float b, uint32_t& hi, uint32_t& lo) {
    float ah = __bfloat162float(__float2bfloat16_rn(a));
    float bh = __bfloat162float(__float2bfloat16_rn(b));
    hi = pk2(ah, bh);
    lo = pk2(a - ah, b - bh);
}
__device__ __forceinline__ void split1(float a, uint16_t& hi, uint16_t& lo) {
    __nv_bfloat16 h = __float2bfloat16_rn(a);
    hi = *(uint16_t*)&h;
    __nv_bfloat16 l = __float2bfloat16_rn(a - __bfloat162float(h));
    lo = *(uint16_t*)&l;
}

// Transpose + split cur_x (B,C,N) -> (B,N,C) bf16 hi/lo
__global__ void transpose_split_kernel(const float* __restrict__ cur) {
    __shared__ float t[32][33];
    int b  = blockIdx.z;
    int c0 = blockIdx.y * 32;
    int n0 = blockIdx.x * 32;
    const float* src = cur + (size_t)b * CCUR * N_;
    #pragma unroll
    for (int r = threadIdx.y; r < 32; r += 8)
        t[r][threadIdx.x] = src[(size_t)(c0 + r) * N_ + n0 + threadIdx.x];
    __syncthreads();
    size_t dbase = (size_t)b * N_ * CCUR;
    #pragma unroll
    for (int r = threadIdx.y; r < 32; r += 8) {
        float v = t[threadIdx.x][r];
        uint16_t hi, lo;
        split1(v, hi, lo);
        size_t o = dbase + (size_t)(n0 + r) * CCUR + c0 + threadIdx.x;
        g_curT_h[o] = hi;
        g_curT_l[o] = lo;
    }
}

// Pre-split W into its smem image: [d][k] rows, hi/lo bf16 pairs
__global__ void wsplit_kernel(const float* __restrict__ w) {
    int i = blockIdx.x * 256 + threadIdx.x;   // 128 d x 96 k-pairs
    if (i >= DOUT * (CIN / 2)) return;
    int d = i & 127, kp = i >> 7;
    float a = w[(size_t)(2 * kp) * DOUT + d];
    float c = w[(size_t)(2 * kp + 1) * DOUT + d];
    uint32_t hi, lo;
    split2(a, c, hi, lo);
    g_wh[d * (SW / 2) + kp] = hi;
    g_wl[d * (SW / 2) + kp] = lo;
}

// ---------------------------------------------------------------------------
__device__ __forceinline__ uint32_t smem_u32(const void* p) {
    uint32_t a;
    asm("{ .reg .u64 t; cvta.to.shared.u64 t, %1; cvt.u32.u64 %0, t; }" : "=r"(a) : "l"(p));
    return a;
}
__device__ __forceinline__ void cp_async16(uint32_t dst, const void* src) {
    asm volatile("cp.async.cg.shared.global [%0], [%1], 16;" :: "r"(dst), "l"(src));
}

#define LDSM4(r0, r1, r2, r3, addr)                                          \
    asm volatile("ldmatrix.sync.aligned.m8n8.x4.shared.b16 {%0,%1,%2,%3}, [%4];" \
                 : "=r"(r0), "=r"(r1), "=r"(r2), "=r"(r3) : "r"(addr))
#define LDSM4T(r0, r1, r2, r3, addr)                                         \
    asm volatile("ldmatrix.sync.aligned.m8n8.x4.trans.shared.b16 {%0,%1,%2,%3}, [%4];" \
                 : "=r"(r0), "=r"(r1), "=r"(r2), "=r"(r3) : "r"(addr))
#define MMA16816(c, a, b)                                                    \
    asm volatile("mma.sync.aligned.m16n8k16.row.col.f32.bf16.bf16.f32 "       \
                 "{%0,%1,%2,%3}, {%4,%5,%6,%7}, {%8,%9}, {%0,%1,%2,%3};"      \
                 : "+f"((c)[0]), "+f"((c)[1]), "+f"((c)[2]), "+f"((c)[3])     \
                 : "r"((a)[0]), "r"((a)[1]), "r"((a)[2]), "r"((a)[3]),        \
                   "r"((b)[0]), "r"((b)[1]))

extern __shared__ char smc[];

__global__ __launch_bounds__(THREADS, 1)
void fused_kernel(const float* __restrict__ pre_x,
                  const int* __restrict__ up_idx,
                  const float* __restrict__ bias,
                  const float* __restrict__ gamma,
                  const float* __restrict__ beta,
                  const float* __restrict__ rmean,
                  const float* __restrict__ rvar,
                  float* __restrict__ out) {
    const int b    = blockIdx.y;
    const int m0   = blockIdx.x * MT;
    const int tid  = threadIdx.x;
    const int wid  = tid >> 5;
    const int lane = tid & 31;

    int*   idx_s = (int*)(smc + SM_IDX);
    float* sc_s  = (float*)(smc + SM_SC);
    float* bi_s  = (float*)(smc + SM_BI);
    const uint32_t base_u32 = smem_u32(smc);

    if (tid < MT) {
        idx_s[tid] = up_idx[(size_t)b * M_ + m0 + tid] & (N_ - 1);
        float s = gamma[tid] * rsqrtf(rvar[tid] + 1e-5f);
        sc_s[tid] = s;
        bi_s[tid] = (bias[tid] - rmean[tid]) * s + beta[tid];
    }

    // ---- group 0: W tiles (cp.async of precomputed smem image) ----
    {
        const char* sh = (const char*)g_wh;
        const char* sl = (const char*)g_wl;
        for (int i = tid; i < 128 * SW * 2 / 16; i += THREADS) {
            cp_async16(base_u32 + SM_WH + 16 * i, sh + 16 * i);
            cp_async16(base_u32 + SM_WL + 16 * i, sl + 16 * i);
        }
        asm volatile("cp.async.commit_group;");
    }
    __syncthreads();   // idx_s visible (W stays in flight)

    // ---- group 1: XG gather rows (cp.async) ----
    {
        const char* sh = (const char*)(g_curT_h + (size_t)b * N_ * CCUR);
        const char* sl = (const char*)(g_curT_l + (size_t)b * N_ * CCUR);
        for (int i = tid; i < 128 * 16; i += THREADS) {
            int m = i >> 4, c = i & 15;
            uint32_t doff = (uint32_t)(m * SXG * 2 + c * 16);
            size_t   soff = (size_t)idx_s[m] * CCUR * 2 + c * 16;
            cp_async16(base_u32 + SM_XGH + doff, sh + soff);
            cp_async16(base_u32 + SM_XGL + doff, sl + soff);
        }
        asm volatile("cp.async.commit_group;");
    }

    // ---- XA: direct fp32 LDG + split + STS (overlaps the two DMA groups;
    //      pre_x has no reuse, so converting here costs nothing extra) ----
    {
        const float* base = pre_x + (size_t)b * CPRE * M_ + m0;
        uint32_t* xah = (uint32_t*)(smc + SM_XAH);
        uint32_t* xal = (uint32_t*)(smc + SM_XAL);
        for (int i = tid; i < CPRE * 64; i += THREADS) {
            int k = i >> 6, mp = i & 63;
            float2 v = *(const float2*)(base + (size_t)k * M_ + 2 * mp);
            uint32_t hi, lo;
            split2(v.x, v.y, hi, lo);
            xah[k * (SXA / 2) + mp] = hi;
            xal[k * (SXA / 2) + mp] = lo;
        }
    }
    asm volatile("cp.async.wait_group 1;" ::: "memory");   // W done; XG may fly
    __syncthreads();                                       // XA + W visible

    // ---- mainloop: warp tile 32m x 32d ----
    const int wm = wid & 3;    // m-quarter (32)
    const int wd = wid >> 2;   // d-quarter (32)
    const int r  = lane & 7;
    const int q  = lane >> 3;

    // pre tile (trans): rows k, cols m
    const int krA = r + ((q >= 2) ? 8 : 0);
    const int mcA = wm * 32 + ((q & 1) ? 8 : 0);
    uint32_t aP_h = base_u32 + SM_XAH + (krA * SXA + mcA) * 2;
    uint32_t aP_l = base_u32 + SM_XAL + (krA * SXA + mcA) * 2;
    // gather tile (non-trans): rows m, cols k'
    const int mrA = wm * 32 + r + ((q & 1) ? 8 : 0);
    const int kcA = (q >= 2) ? 8 : 0;
    uint32_t aG_h = base_u32 + SM_XGH + (mrA * SXG + kcA) * 2;
    uint32_t aG_l = base_u32 + SM_XGL + (mrA * SXG + kcA) * 2;
    // w tile (non-trans): rows d, cols k
    const int drB = wd * 32 + r + ((q >= 2) ? 8 : 0);
    const int kcB = (q & 1) ? 8 : 0;
    uint32_t bW_h = base_u32 + SM_WH + (drB * SW + kcB) * 2;
    uint32_t bW_l = base_u32 + SM_WL + (drB * SW + kcB) * 2;

    float acc[2][4][4];
    #pragma unroll
    for (int i = 0; i < 2; i++)
        #pragma unroll
        for (int j = 0; j < 4; j++)
            #pragma unroll
            for (int e = 0; e < 4; e++) acc[i][j][e] = 0.0f;

    uint32_t ah[2][4], al[2][4], bh[4][2], bl[4][2];

    // ksteps 0..3: pre_x region (k-major, trans LDSM) — XG still landing
    #pragma unroll
    for (int ks = 0; ks < 4; ks++) {
        const int k0 = ks * 16;
        #pragma unroll
        for (int mf = 0; mf < 2; mf++) {
            uint32_t o = (uint32_t)(k0 * SXA + mf * 16) * 2;
            LDSM4T(ah[mf][0], ah[mf][1], ah[mf][2], ah[mf][3], aP_h + o);
            LDSM4T(al[mf][0], al[mf][1], al[mf][2], al[mf][3], aP_l + o);
        }
        #pragma unroll
        for (int g = 0; g < 2; g++) {
            uint32_t o = (uint32_t)(g * 16 * SW + k0) * 2;
            LDSM4(bh[2*g][0], bh[2*g][1], bh[2*g+1][0], bh[2*g+1][1], bW_h + o);
            LDSM4(bl[2*g][0], bl[2*g][1], bl[2*g+1][0], bl[2*g+1][1], bW_l + o);
        }
        #pragma unroll
        for (int mf = 0; mf < 2; mf++)
            #pragma unroll
            for (int nf = 0; nf < 4; nf++) MMA16816(acc[mf][nf], ah[mf], bh[nf]);
        #pragma unroll
        for (int mf = 0; mf < 2; mf++)
            #pragma unroll
            for (int nf = 0; nf < 4; nf++) MMA16816(acc[mf][nf], ah[mf], bl[nf]);
        #pragma unroll
        for (int mf = 0; mf < 2; mf++)
            #pragma unroll
            for (int nf = 0; nf < 4; nf++) MMA16816(acc[mf][nf], al[mf], bh[nf]);
    }

    asm volatile("cp.async.wait_group 0;" ::: "memory");   // XG done
    __syncthreads();

    // ksteps 4..11: gather region (m-major, non-trans LDSM)
    #pragma unroll
    for (int ks = 4; ks < 12; ks++) {
        const int k0  = ks * 16;
        const int kp0 = k0 - 64;
        #pragma unroll
        for (int mf = 0; mf < 2; mf++) {
            uint32_t o = (uint32_t)(mf * 16 * SXG + kp0) * 2;
            LDSM4(ah[mf][0], ah[mf][1], ah[mf][2], ah[mf][3], aG_h + o);
            LDSM4(al[mf][0], al[mf][1], al[mf][2], al[mf][3], aG_l + o);
        }
        #pragma unroll
        for (int g = 0; g < 2; g++) {
            uint32_t o = (uint32_t)(g * 16 * SW + k0) * 2;
            LDSM4(bh[2*g][0], bh[2*g][1], bh[2*g+1][0], bh[2*g+1][1], bW_h + o);
            LDSM4(bl[2*g][0], bl[2*g][1], bl[2*g+1][0], bl[2*g+1][1], bW_l + o);
        }
        #pragma unroll
        for (int mf = 0; mf < 2; mf++)
            #pragma unroll
            for (int nf = 0; nf < 4; nf++) MMA16816(acc[mf][nf], ah[mf], bh[nf]);
        #pragma unroll
        for (int mf = 0; mf < 2; mf++)
            #pragma unroll
            for (int nf = 0; nf < 4; nf++) MMA16816(acc[mf][nf], ah[mf], bl[nf]);
        #pragma unroll
        for (int mf = 0; mf < 2; mf++)
            #pragma unroll
            for (int nf = 0; nf < 4; nf++) MMA16816(acc[mf][nf], al[mf], bh[nf]);
    }

    // ---- epilogue: BN + ReLU + STG.64 ----
    const int gid = lane >> 2;
    const int tig = lane & 3;
    const size_t obase = ((size_t)b * M_ + m0) * DOUT;

    #pragma unroll
    for (int nf = 0; nf < 4; nf++) {
        int d0 = wd * 32 + nf * 8 + 2 * tig;
        float s0 = sc_s[d0], s1 = sc_s[d0 + 1];
        float b0 = bi_s[d0], b1 = bi_s[d0 + 1];
        #pragma unroll
        for (int mf = 0; mf < 2; mf++) {
            int rA = wm * 32 + mf * 16 + gid;
            int rB = rA + 8;
            float2 v0, v1;
            v0.x = fmaxf(fmaf(acc[mf][nf][0], s0, b0), 0.0f);
            v0.y = fmaxf(fmaf(acc[mf][nf][1], s1, b1), 0.0f);
            v1.x = fmaxf(fmaf(acc[mf][nf][2], s0, b0), 0.0f);
            v1.y = fmaxf(fmaf(acc[mf][nf][3], s1, b1), 0.0f);
            *(float2*)(out + obase + (size_t)rA * DOUT + d0) = v0;
            *(float2*)(out + obase + (size_t)rB * DOUT + d0) = v1;
        }
    }
}

// ---------------------------------------------------------------------------
extern "C" void kernel_launch(void* const* d_in, const int* in_sizes, int n_in,
                              void* d_out, int out_size) {
    const float* pre_x  = (const float*)d_in[0];
    const float* cur_x  = (const float*)d_in[1];
    const int*   up_idx = (const int*)d_in[2];
    const float* w      = (const float*)d_in[3];
    const float* bias   = (const float*)d_in[4];
    const float* gamma  = (const float*)d_in[5];
    const float* beta   = (const float*)d_in[6];
    const float* rmean  = (const float*)d_in[7];
    const float* rvar   = (const float*)d_in[8];
    float*       out    = (float*)d_out;

    dim3 tg(N_ / 32, CCUR / 32, B_);
    transpose_split_kernel<<<tg, dim3(32, 8)>>>(cur_x);
    wsplit_kernel<<<48, 256>>>(w);

    cudaFuncSetAttribute(fused_kernel, cudaFuncAttributeMaxDynamicSharedMemorySize, SM_TOT);
    dim3 grid(M_ / MT, B_);
    fused_kernel<<<grid, THREADS, SM_TOT>>>(pre_x, up_idx, bias, gamma, beta,
                                            rmean, rvar, out);
}

// round 11
// speedup vs baseline: 1.2122x; 1.2122x over previous
#include <cuda_runtime.h>
#include <cuda_bf16.h>
#include <cstdint>

// Problem constants
constexpr int B_   = 4;
constexpr int M_   = 65536;
constexpr int N_   = 16384;
constexpr int CPRE = 64;
constexpr int CCUR = 128;
constexpr int CIN  = 192;
constexpr int DOUT = 128;

constexpr int MT      = 64;         // m-tile (persistent, double-buffered)
constexpr int THREADS = 512;        // 16 warps
constexpr int GRID    = 148;        // persistent: 1 CTA/SM
constexpr int NTILES  = (M_ / MT) * B_;   // 4096

// SMEM strides (bf16 elems; word stride ≡ 4 mod 8 -> conflict-free LDSM; rows 16B-aligned)
constexpr int SXA = 72;    // pre_x tile, k-major: [64 k][64 m + pad]   (144 B/row)
constexpr int SXG = 136;   // gather tile, m-major: [64 m][128 k' + pad](272 B/row)
constexpr int SW  = 200;   // w tile, d-major: [128 d][192 k + pad]     (400 B/row)

// Buffer-internal offsets
constexpr int XA_BYTES = 64 * SXA * 2;    // 9216
constexpr int XG_BYTES = 64 * SXG * 2;    // 17408
constexpr int BUF_XAH = 0;
constexpr int BUF_XAL = XA_BYTES;
constexpr int BUF_XGH = 2 * XA_BYTES;
constexpr int BUF_XGL = 2 * XA_BYTES + XG_BYTES;
constexpr int BUF_SZ  = 2 * XA_BYTES + 2 * XG_BYTES;   // 53248

constexpr int SM_IDX  = 0;      // 2 x 64 int
constexpr int SM_SC   = 512;
constexpr int SM_BI   = 1024;
constexpr int SM_BUF0 = 1536;
constexpr int SM_BUF1 = SM_BUF0 + BUF_SZ;
constexpr int SM_WH   = SM_BUF1 + BUF_SZ;            // 108032
constexpr int SM_WL   = SM_WH + 128 * SW * 2;        // +51200
constexpr int SM_TOT  = SM_WL + 128 * SW * 2;        // 210432 (~205.5 KB)

// Pre-split scratch: ONLY data with cross-block reuse + streamed pre_x (keeps
// the fused kernel conversion-free; round-10 in-kernel convert regressed).
__device__ uint16_t g_curT_h[(size_t)B_ * N_ * CCUR];   // (B,N,C) 16 MiB
__device__ uint16_t g_curT_l[(size_t)B_ * N_ * CCUR];
__device__ uint16_t g_pre_h[(size_t)B_ * CPRE * M_];    // (B,C,M) 16 MiB
__device__ uint16_t g_pre_l[(size_t)B_ * CPRE * M_];
__device__ uint32_t g_wh[128 * (SW / 2)];               // W hi smem image [d][k/2]
__device__ uint32_t g_wl[128 * (SW / 2)];

// ---------------------------------------------------------------------------
__device__ __forceinline__ uint32_t pk2(float a, float b) {
    __nv_bfloat162 t = __floats2bfloat162_rn(a, b);
    return *(uint32_t*)&t;
}
__device__ __forceinline__ void split2(float a, float b, uint32_t& hi, uint32_t& lo) {
    float ah = __bfloat162float(__float2bfloat16_rn(a));
    float bh = __bfloat162float(__float2bfloat16_rn(b));
    hi = pk2(ah, bh);
    lo = pk2(a - ah, b - bh);
}
__device__ __forceinline__ void split1(float a, uint16_t& hi, uint16_t& lo) {
    __nv_bfloat16 h = __float2bfloat16_rn(a);
    hi = *(uint16_t*)&h;
    __nv_bfloat16 l = __float2bfloat16_rn(a - __bfloat162float(h));
    lo = *(uint16_t*)&l;
}

// Transpose + split cur_x (B,C,N) -> (B,N,C) bf16 hi/lo
__global__ void transpose_split_kernel(const float* __restrict__ cur) {
    __shared__ float t[32][33];
    int b  = blockIdx.z;
    int c0 = blockIdx.y * 32;
    int n0 = blockIdx.x * 32;
    const float* src = cur + (size_t)b * CCUR * N_;
    #pragma unroll
    for (int r = threadIdx.y; r < 32; r += 8)
        t[r][threadIdx.x] = src[(size_t)(c0 + r) * N_ + n0 + threadIdx.x];
    __syncthreads();
    size_t dbase = (size_t)b * N_ * CCUR;
    #pragma unroll
    for (int r = threadIdx.y; r < 32; r += 8) {
        float v = t[threadIdx.x][r];
        uint16_t hi, lo;
        split1(v, hi, lo);
        size_t o = dbase + (size_t)(n0 + r) * CCUR + c0 + threadIdx.x;
        g_curT_h[o] = hi;
        g_curT_l[o] = lo;
    }
}

// Elementwise split pre_x (B,C,M) -> bf16 hi/lo (pair-packed)
__global__ void presplit_kernel(const float* __restrict__ pre) {
    size_t i = (size_t)blockIdx.x * blockDim.x + threadIdx.x;   // pair index
    if (i >= (size_t)B_ * CPRE * M_ / 2) return;
    float2 v = ((const float2*)pre)[i];
    uint32_t hi, lo;
    split2(v.x, v.y, hi, lo);
    ((uint32_t*)g_pre_h)[i] = hi;
    ((uint32_t*)g_pre_l)[i] = lo;
}

// Pre-split W into its smem image: [d][k] rows, hi/lo bf16 pairs
__global__ void wsplit_kernel(const float* __restrict__ w) {
    int i = blockIdx.x * 256 + threadIdx.x;   // 128 d x 96 k-pairs
    if (i >= DOUT * (CIN / 2)) return;
    int d = i & 127, kp = i >> 7;
    float a = w[(size_t)(2 * kp) * DOUT + d];
    float c = w[(size_t)(2 * kp + 1) * DOUT + d];
    uint32_t hi, lo;
    split2(a, c, hi, lo);
    g_wh[d * (SW / 2) + kp] = hi;
    g_wl[d * (SW / 2) + kp] = lo;
}

// ---------------------------------------------------------------------------
__device__ __forceinline__ uint32_t smem_u32(const void* p) {
    uint32_t a;
    asm("{ .reg .u64 t; cvta.to.shared.u64 t, %1; cvt.u32.u64 %0, t; }" : "=r"(a) : "l"(p));
    return a;
}
__device__ __forceinline__ void cp_async16(uint32_t dst, const void* src) {
    asm volatile("cp.async.cg.shared.global [%0], [%1], 16;" :: "r"(dst), "l"(src));
}

#define LDSM4(r0, r1, r2, r3, addr)                                          \
    asm volatile("ldmatrix.sync.aligned.m8n8.x4.shared.b16 {%0,%1,%2,%3}, [%4];" \
                 : "=r"(r0), "=r"(r1), "=r"(r2), "=r"(r3) : "r"(addr))
#define LDSM4T(r0, r1, r2, r3, addr)                                         \
    asm volatile("ldmatrix.sync.aligned.m8n8.x4.trans.shared.b16 {%0,%1,%2,%3}, [%4];" \
                 : "=r"(r0), "=r"(r1), "=r"(r2), "=r"(r3) : "r"(addr))
#define MMA16816(c, a, b)                                                    \
    asm volatile("mma.sync.aligned.m16n8k16.row.col.f32.bf16.bf16.f32 "       \
                 "{%0,%1,%2,%3}, {%4,%5,%6,%7}, {%8,%9}, {%0,%1,%2,%3};"      \
                 : "+f"((c)[0]), "+f"((c)[1]), "+f"((c)[2]), "+f"((c)[3])     \
                 : "r"((a)[0]), "r"((a)[1]), "r"((a)[2]), "r"((a)[3]),        \
                   "r"((b)[0]), "r"((b)[1]))

extern __shared__ char smc[];

__global__ __launch_bounds__(THREADS, 1)
void fused_kernel(const int* __restrict__ up_idx,
                  const float* __restrict__ bias,
                  const float* __restrict__ gamma,
                  const float* __restrict__ beta,
                  const float* __restrict__ rmean,
                  const float* __restrict__ rvar,
                  float* __restrict__ out) {
    const int bid  = blockIdx.x;
    const int tid  = threadIdx.x;
    const int wid  = tid >> 5;
    const int lane = tid & 31;

    int*   idx_s = (int*)(smc + SM_IDX);     // [2][64]
    float* sc_s  = (float*)(smc + SM_SC);
    float* bi_s  = (float*)(smc + SM_BI);
    const uint32_t base_u32 = smem_u32(smc);

    const int nt = (NTILES - 1 - bid) / GRID + 1;   // tiles for this CTA

    // ---- load idx for a tile into a slot (64 threads) ----
    auto load_idx = [&](int i_local, int slot) {
        int tt = bid + i_local * GRID;
        if (tid < MT && i_local < nt) {
            int b  = tt >> 10;
            int m0 = (tt & 1023) << 6;
            idx_s[slot * MT + tid] = up_idx[(size_t)b * M_ + m0 + tid] & (N_ - 1);
        }
    };

    // ---- stage one X tile via cp.async (pure copies, no conversion) ----
    auto stage_X = [&](int i_local, int bufp) {
        int tt = bid + i_local * GRID;
        int b  = tt >> 10;
        int m0 = (tt & 1023) << 6;
        uint32_t bb = base_u32 + (bufp ? SM_BUF1 : SM_BUF0);
        // XA: 64 k-rows x 128B (one 16B chunk per thread per hi/lo)
        {
            const char* sh = (const char*)(g_pre_h + (size_t)b * CPRE * M_ + m0);
            const char* sl = (const char*)(g_pre_l + (size_t)b * CPRE * M_ + m0);
            int k = tid >> 3, c = tid & 7;
            size_t soff = (size_t)k * M_ * 2 + c * 16;
            uint32_t doff = (uint32_t)(k * (SXA * 2) + c * 16);
            cp_async16(bb + BUF_XAH + doff, sh + soff);
            cp_async16(bb + BUF_XAL + doff, sl + soff);
        }
        // XG: 64 gathered rows x 256B
        {
            const char* sh = (const char*)(g_curT_h + (size_t)b * N_ * CCUR);
            const char* sl = (const char*)(g_curT_l + (size_t)b * N_ * CCUR);
            const int* idxp = idx_s + (i_local & 1) * MT;
            #pragma unroll
            for (int i = tid; i < MT * 16; i += THREADS) {
                int m = i >> 4, c = i & 15;
                size_t soff = (size_t)idxp[m] * (CCUR * 2) + c * 16;
                uint32_t doff = (uint32_t)(m * (SXG * 2) + c * 16);
                cp_async16(bb + BUF_XGH + doff, sh + soff);
                cp_async16(bb + BUF_XGL + doff, sl + soff);
            }
        }
    };

    // ---- prologue ----
    if (tid < DOUT) {
        float s = gamma[tid] * rsqrtf(rvar[tid] + 1e-5f);
        sc_s[tid] = s;
        bi_s[tid] = (bias[tid] - rmean[tid]) * s + beta[tid];
    }
    load_idx(0, 0);
    __syncthreads();

    // G0: W (once per CTA!) + tile 0
    {
        const char* sh = (const char*)g_wh;
        const char* sl = (const char*)g_wl;
        for (int i = tid; i < 128 * SW * 2 / 16; i += THREADS) {
            cp_async16(base_u32 + SM_WH + 16 * i, sh + 16 * i);
            cp_async16(base_u32 + SM_WL + 16 * i, sl + 16 * i);
        }
    }
    stage_X(0, 0);
    asm volatile("cp.async.commit_group;");
    load_idx(1, 1);

    // per-lane constant fragments of ldmatrix addressing
    const int wm = wid & 3;    // m-quarter (16 m)
    const int wd = wid >> 2;   // d-quarter (32 d)
    const int r  = lane & 7;
    const int q  = lane >> 3;
    // XA (trans): rows k, cols m
    const uint32_t oA = (uint32_t)((r + ((q >= 2) ? 8 : 0)) * SXA +
                                   wm * 16 + ((q & 1) ? 8 : 0)) * 2;
    // XG (non-trans): rows m, cols k'
    const uint32_t oG = (uint32_t)((wm * 16 + r + ((q & 1) ? 8 : 0)) * SXG +
                                   ((q >= 2) ? 8 : 0)) * 2;
    // W (non-trans): rows d, cols k
    uint32_t bW_h = base_u32 + SM_WH +
                    (uint32_t)((wd * 32 + r + ((q >= 2) ? 8 : 0)) * SW +
                               ((q & 1) ? 8 : 0)) * 2;
    uint32_t bW_l = bW_h + (SM_WL - SM_WH);

    const int gid = lane >> 2;
    const int tig = lane & 3;

    // ---- persistent tile loop ----
    for (int i = 0; i < nt; i++) {
        __syncthreads();                       // idx[(i+1)&1] visible; buf[(i+1)&1] free
        if (i + 1 < nt) stage_X(i + 1, (i + 1) & 1);
        asm volatile("cp.async.commit_group;");          // G_{i+1} (may be empty)
        asm volatile("cp.async.wait_group 1;" ::: "memory");   // G_i done
        __syncthreads();                       // buf[i&1] + (i==0: W) visible to all

        const uint32_t bb = base_u32 + ((i & 1) ? SM_BUF1 : SM_BUF0);
        const uint32_t aXA_h = bb + BUF_XAH + oA, aXA_l = bb + BUF_XAL + oA;
        const uint32_t aXG_h = bb + BUF_XGH + oG, aXG_l = bb + BUF_XGL + oG;

        float acc[4][4];
        #pragma unroll
        for (int j = 0; j < 4; j++)
            #pragma unroll
            for (int e = 0; e < 4; e++) acc[j][e] = 0.0f;

        uint32_t ah[4], al[4], bh[4][2], bl[4][2];

        // ksteps 0..3: pre_x region (k-major, trans LDSM)
        #pragma unroll
        for (int ks = 0; ks < 4; ks++) {
            const int k0 = ks * 16;
            {
                uint32_t o = (uint32_t)(k0 * SXA) * 2;
                LDSM4T(ah[0], ah[1], ah[2], ah[3], aXA_h + o);
                LDSM4T(al[0], al[1], al[2], al[3], aXA_l + o);
            }
            #pragma unroll
            for (int g = 0; g < 2; g++) {
                uint32_t o = (uint32_t)(g * 16 * SW + k0) * 2;
                LDSM4(bh[2*g][0], bh[2*g][1], bh[2*g+1][0], bh[2*g+1][1], bW_h + o);
                LDSM4(bl[2*g][0], bl[2*g][1], bl[2*g+1][0], bl[2*g+1][1], bW_l + o);
            }
            #pragma unroll
            for (int nf = 0; nf < 4; nf++) MMA16816(acc[nf], ah, bh[nf]);
            #pragma unroll
            for (int nf = 0; nf < 4; nf++) MMA16816(acc[nf], ah, bl[nf]);
            #pragma unroll
            for (int nf = 0; nf < 4; nf++) MMA16816(acc[nf], al, bh[nf]);
        }
        // ksteps 4..11: gather region (m-major, non-trans LDSM)
        #pragma unroll
        for (int ks = 4; ks < 12; ks++) {
            const int k0  = ks * 16;
            const int kp0 = k0 - 64;
            {
                uint32_t o = (uint32_t)kp0 * 2;
                LDSM4(ah[0], ah[1], ah[2], ah[3], aXG_h + o);
                LDSM4(al[0], al[1], al[2], al[3], aXG_l + o);
            }
            #pragma unroll
            for (int g = 0; g < 2; g++) {
                uint32_t o = (uint32_t)(g * 16 * SW + k0) * 2;
                LDSM4(bh[2*g][0], bh[2*g][1], bh[2*g+1][0], bh[2*g+1][1], bW_h + o);
                LDSM4(bl[2*g][0], bl[2*g][1], bl[2*g+1][0], bl[2*g+1][1], bW_l + o);
            }
            #pragma unroll
            for (int nf = 0; nf < 4; nf++) MMA16816(acc[nf], ah, bh[nf]);
            #pragma unroll
            for (int nf = 0; nf < 4; nf++) MMA16816(acc[nf], ah, bl[nf]);
            #pragma unroll
            for (int nf = 0; nf < 4; nf++) MMA16816(acc[nf], al, bh[nf]);
        }

        // ---- epilogue: BN + ReLU + STG.64 ----
        {
            int tt = bid + i * GRID;
            int b  = tt >> 10;
            int m0 = (tt & 1023) << 6;
            const size_t obase = ((size_t)b * M_ + m0) * DOUT;
            #pragma unroll
            for (int nf = 0; nf < 4; nf++) {
                int d0 = wd * 32 + nf * 8 + 2 * tig;
                float s0 = sc_s[d0], s1 = sc_s[d0 + 1];
                float b0 = bi_s[d0], b1 = bi_s[d0 + 1];
                int rA = wm * 16 + gid;
                float2 v0, v1;
                v0.x = fmaxf(fmaf(acc[nf][0], s0, b0), 0.0f);
                v0.y = fmaxf(fmaf(acc[nf][1], s1, b1), 0.0f);
                v1.x = fmaxf(fmaf(acc[nf][2], s0, b0), 0.0f);
                v1.y = fmaxf(fmaf(acc[nf][3], s1, b1), 0.0f);
                *(float2*)(out + obase + (size_t)rA * DOUT + d0)       = v0;
                *(float2*)(out + obase + (size_t)(rA + 8) * DOUT + d0) = v1;
            }
        }

        load_idx(i + 2, i & 1);   // idx for tile i+2 into slot (i+2)&1 == i&1
    }
}

// ---------------------------------------------------------------------------
extern "C" void kernel_launch(void* const* d_in, const int* in_sizes, int n_in,
                              void* d_out, int out_size) {
    const float* pre_x  = (const float*)d_in[0];
    const float* cur_x  = (const float*)d_in[1];
    const int*   up_idx = (const int*)d_in[2];
    const float* w      = (const float*)d_in[3];
    const float* bias   = (const float*)d_in[4];
    const float* gamma  = (const float*)d_in[5];
    const float* beta   = (const float*)d_in[6];
    const float* rmean  = (const float*)d_in[7];
    const float* rvar   = (const float*)d_in[8];
    float*       out    = (float*)d_out;

    dim3 tg(N_ / 32, CCUR / 32, B_);
    transpose_split_kernel<<<tg, dim3(32, 8)>>>(cur_x);
    presplit_kernel<<<(int)(((size_t)B_ * CPRE * M_ / 2 + 255) / 256), 256>>>(pre_x);
    wsplit_kernel<<<48, 256>>>(w);

    cudaFuncSetAttribute(fused_kernel, cudaFuncAttributeMaxDynamicSharedMemorySize, SM_TOT);
    fused_kernel<<<GRID, THREADS, SM_TOT>>>(up_idx, bias, gamma, beta,
                                            rmean, rvar, out);
}

// round 13
// speedup vs baseline: 1.5874x; 1.3096x over previous
#include <cuda_runtime.h>
#include <cuda_fp16.h>
#include <cstdint>

// Problem constants
constexpr int B_   = 4;
constexpr int M_   = 65536;
constexpr int N_   = 16384;
constexpr int CPRE = 64;
constexpr int CCUR = 128;
constexpr int CIN  = 192;
constexpr int DOUT = 128;

constexpr int MT      = 64;      // m-tile (persistent, double-buffered)
constexpr int THREADS = 256;     // 8 warps (leaves regs for W-fragment hoist)
constexpr int GRID    = 148;     // persistent: 1 CTA/SM
constexpr int NTILES  = (M_ / MT) * B_;   // 4096

// SMEM strides (fp16 elems; word stride ≡ 4 mod 8 -> conflict-free LDSM)
constexpr int SXA = 72;    // pre_x tile, k-major: [64 k][64 m + pad]
constexpr int SXG = 136;   // gather tile, m-major: [64 m][128 k' + pad]
constexpr int SW  = 200;   // w tile, d-major: [128 d][192 k + pad]

constexpr int XA_BYTES = 64 * SXA * 2;    // 9216
constexpr int XG_BYTES = 64 * SXG * 2;    // 17408
constexpr int BUF_XA   = 0;
constexpr int BUF_XG   = XA_BYTES;
constexpr int BUF_SZ   = XA_BYTES + XG_BYTES;   // 26624

constexpr int SM_IDX  = 0;      // 2 x 64 int
constexpr int SM_SC   = 512;
constexpr int SM_BI   = 1024;
constexpr int SM_BUF0 = 1536;
constexpr int SM_BUF1 = SM_BUF0 + BUF_SZ;
constexpr int SM_WH   = SM_BUF1 + BUF_SZ;      // 54784
constexpr int SM_WL   = SM_WH + 128 * SW * 2;  // +51200
constexpr int SM_TOT  = SM_WL + 128 * SW * 2;  // 157184 (~153.5 KB)

// Pre-converted scratch (fp16 single for x: 2-pass split drops x-lo entirely)
__device__ __half   g_curT[(size_t)B_ * N_ * CCUR];   // (B,N,C) 16 MiB
__device__ __half   g_pre[(size_t)B_ * CPRE * M_];    // (B,C,M) 32 MiB
__device__ uint32_t g_wh[128 * (SW / 2)];             // W hi smem image [d][k/2]
__device__ uint32_t g_wl[128 * (SW / 2)];             // W lo (fp16 residual)

// ---------------------------------------------------------------------------
__device__ __forceinline__ uint32_t pk2h(float a, float b) {
    __half2 t = __floats2half2_rn(a, b);
    return *(uint32_t*)&t;
}

// Transpose + fp16-convert cur_x (B,C,N) -> (B,N,C)
__global__ void transpose_split_kernel(const float* __restrict__ cur) {
    __shared__ float t[32][33];
    int b  = blockIdx.z;
    int c0 = blockIdx.y * 32;
    int n0 = blockIdx.x * 32;
    const float* src = cur + (size_t)b * CCUR * N_;
    #pragma unroll
    for (int r = threadIdx.y; r < 32; r += 8)
        t[r][threadIdx.x] = src[(size_t)(c0 + r) * N_ + n0 + threadIdx.x];
    __syncthreads();
    size_t dbase = (size_t)b * N_ * CCUR;
    #pragma unroll
    for (int r = threadIdx.y; r < 32; r += 8)
        g_curT[dbase + (size_t)(n0 + r) * CCUR + c0 + threadIdx.x] =
            __float2half_rn(t[threadIdx.x][r]);
}

// Elementwise fp16-convert pre_x (pair-packed stores)
__global__ void presplit_kernel(const float* __restrict__ pre) {
    size_t i = (size_t)blockIdx.x * blockDim.x + threadIdx.x;   // pair index
    if (i >= (size_t)B_ * CPRE * M_ / 2) return;
    float2 v = ((const float2*)pre)[i];
    ((uint32_t*)g_pre)[i] = pk2h(v.x, v.y);
}

// W -> fp16 hi/lo smem images [d][k] (pair-packed along k)
__global__ void wsplit_kernel(const float* __restrict__ w) {
    int i = blockIdx.x * 256 + threadIdx.x;   // 128 d x 96 k-pairs
    if (i >= DOUT * (CIN / 2)) return;
    int d = i & 127, kp = i >> 7;
    float a = w[(size_t)(2 * kp) * DOUT + d];
    float c = w[(size_t)(2 * kp + 1) * DOUT + d];
    float ah = __half2float(__float2half_rn(a));
    float ch = __half2float(__float2half_rn(c));
    g_wh[d * (SW / 2) + kp] = pk2h(ah, ch);
    g_wl[d * (SW / 2) + kp] = pk2h(a - ah, c - ch);
}

// ---------------------------------------------------------------------------
__device__ __forceinline__ uint32_t smem_u32(const void* p) {
    uint32_t a;
    asm("{ .reg .u64 t; cvta.to.shared.u64 t, %1; cvt.u32.u64 %0, t; }" : "=r"(a) : "l"(p));
    return a;
}
__device__ __forceinline__ void cp_async16(uint32_t dst, const void* src) {
    asm volatile("cp.async.cg.shared.global [%0], [%1], 16;" :: "r"(dst), "l"(src));
}

#define LDSM4(r0, r1, r2, r3, addr)                                          \
    asm volatile("ldmatrix.sync.aligned.m8n8.x4.shared.b16 {%0,%1,%2,%3}, [%4];" \
                 : "=r"(r0), "=r"(r1), "=r"(r2), "=r"(r3) : "r"(addr))
#define LDSM4T(r0, r1, r2, r3, addr)                                         \
    asm volatile("ldmatrix.sync.aligned.m8n8.x4.trans.shared.b16 {%0,%1,%2,%3}, [%4];" \
                 : "=r"(r0), "=r"(r1), "=r"(r2), "=r"(r3) : "r"(addr))
#define MMAF16(c, a, b)                                                      \
    asm volatile("mma.sync.aligned.m16n8k16.row.col.f32.f16.f16.f32 "         \
                 "{%0,%1,%2,%3}, {%4,%5,%6,%7}, {%8,%9}, {%0,%1,%2,%3};"      \
                 : "+f"((c)[0]), "+f"((c)[1]), "+f"((c)[2]), "+f"((c)[3])     \
                 : "r"((a)[0]), "r"((a)[1]), "r"((a)[2]), "r"((a)[3]),        \
                   "r"((b)[0]), "r"((b)[1]))

extern __shared__ char smc[];

__global__ __launch_bounds__(THREADS, 1)
void fused_kernel(const int* __restrict__ up_idx,
                  const float* __restrict__ bias,
                  const float* __restrict__ gamma,
                  const float* __restrict__ beta,
                  const float* __restrict__ rmean,
                  const float* __restrict__ rvar,
                  float* __restrict__ out) {
    const int bid  = blockIdx.x;
    const int tid  = threadIdx.x;
    const int wid  = tid >> 5;
    const int lane = tid & 31;

    int*   idx_s = (int*)(smc + SM_IDX);     // [2][64]
    float* sc_s  = (float*)(smc + SM_SC);
    float* bi_s  = (float*)(smc + SM_BI);
    const uint32_t base_u32 = smem_u32(smc);

    const int nt = (NTILES - 1 - bid) / GRID + 1;

    auto load_idx = [&](int i_local, int slot) {
        int tt = bid + i_local * GRID;
        if (tid < MT && i_local < nt) {
            int b  = tt >> 10;
            int m0 = (tt & 1023) << 6;
            idx_s[slot * MT + tid] = up_idx[(size_t)b * M_ + m0 + tid] & (N_ - 1);
        }
    };

    auto stage_X = [&](int i_local, int bufp) {
        int tt = bid + i_local * GRID;
        int b  = tt >> 10;
        int m0 = (tt & 1023) << 6;
        uint32_t bb = base_u32 + (bufp ? SM_BUF1 : SM_BUF0);
        // XA: 64 k-rows x 128B
        {
            const char* s = (const char*)(g_pre + (size_t)b * CPRE * M_ + m0);
            #pragma unroll
            for (int i = tid; i < 64 * 8; i += THREADS) {
                int k = i >> 3, c = i & 7;
                cp_async16(bb + BUF_XA + (uint32_t)(k * (SXA * 2) + c * 16),
                           s + (size_t)k * M_ * 2 + c * 16);
            }
        }
        // XG: 64 gathered rows x 256B
        {
            const char* s = (const char*)(g_curT + (size_t)b * N_ * CCUR);
            const int* idxp = idx_s + (i_local & 1) * MT;
            #pragma unroll
            for (int i = tid; i < 64 * 16; i += THREADS) {
                int m = i >> 4, c = i & 15;
                cp_async16(bb + BUF_XG + (uint32_t)(m * (SXG * 2) + c * 16),
                           s + (size_t)idxp[m] * (CCUR * 2) + c * 16);
            }
        }
    };

    // ---- prologue ----
    if (tid < DOUT) {
        float s = gamma[tid] * rsqrtf(rvar[tid] + 1e-5f);
        sc_s[tid] = s;
        bi_s[tid] = (bias[tid] - rmean[tid]) * s + beta[tid];
    }
    load_idx(0, 0);
    __syncthreads();

    // G0: W (once per CTA)
    {
        const char* sh = (const char*)g_wh;
        const char* sl = (const char*)g_wl;
        for (int i = tid; i < 128 * SW * 2 / 16; i += THREADS) {
            cp_async16(base_u32 + SM_WH + 16 * i, sh + 16 * i);
            cp_async16(base_u32 + SM_WL + 16 * i, sl + 16 * i);
        }
        asm volatile("cp.async.commit_group;");
    }
    // G1: tile 0
    stage_X(0, 0);
    asm volatile("cp.async.commit_group;");
    load_idx(1, 1);

    asm volatile("cp.async.wait_group 1;" ::: "memory");   // W done
    __syncthreads();

    // per-lane ldmatrix addressing
    const int wm = wid & 1;    // m-half (32 m)
    const int wd = wid >> 1;   // d-quarter (32 d)
    const int r  = lane & 7;
    const int q  = lane >> 3;
    const uint32_t oA = (uint32_t)((r + ((q >= 2) ? 8 : 0)) * SXA +
                                   wm * 32 + ((q & 1) ? 8 : 0)) * 2;
    const uint32_t oG = (uint32_t)((wm * 32 + r + ((q & 1) ? 8 : 0)) * SXG +
                                   ((q >= 2) ? 8 : 0)) * 2;
    const uint32_t bW_h = base_u32 + SM_WH +
                          (uint32_t)((wd * 32 + r + ((q >= 2) ? 8 : 0)) * SW +
                                     ((q & 1) ? 8 : 0)) * 2;
    const uint32_t bW_l = bW_h + (SM_WL - SM_WH);

    // ---- hoist W-hi fragments into registers (tile-invariant!) ----
    uint32_t whf[12][4][2];
    #pragma unroll
    for (int ks = 0; ks < 12; ks++)
        #pragma unroll
        for (int g = 0; g < 2; g++)
            LDSM4(whf[ks][2*g][0], whf[ks][2*g][1],
                  whf[ks][2*g+1][0], whf[ks][2*g+1][1],
                  bW_h + (uint32_t)(g * 16 * SW + ks * 16) * 2);

    const int gid = lane >> 2;
    const int tig = lane & 3;

    // ---- persistent tile loop ----
    for (int i = 0; i < nt; i++) {
        __syncthreads();                         // buf (i+1)&1 free; idx slot visible
        if (i + 1 < nt) stage_X(i + 1, (i + 1) & 1);
        asm volatile("cp.async.commit_group;");
        asm volatile("cp.async.wait_group 1;" ::: "memory");   // tile i done
        __syncthreads();

        const uint32_t bb  = base_u32 + ((i & 1) ? SM_BUF1 : SM_BUF0);
        const uint32_t aXA = bb + BUF_XA + oA;
        const uint32_t aXG = bb + BUF_XG + oG;

        float acc[2][4][4];
        #pragma unroll
        for (int mf = 0; mf < 2; mf++)
            #pragma unroll
            for (int j = 0; j < 4; j++)
                #pragma unroll
                for (int e = 0; e < 4; e++) acc[mf][j][e] = 0.0f;

        uint32_t ah[2][4], bl[4][2];

        // ksteps 0..3: pre_x region (k-major, trans LDSM)
        #pragma unroll
        for (int ks = 0; ks < 4; ks++) {
            const int k0 = ks * 16;
            #pragma unroll
            for (int mf = 0; mf < 2; mf++)
                LDSM4T(ah[mf][0], ah[mf][1], ah[mf][2], ah[mf][3],
                       aXA + (uint32_t)(k0 * SXA + mf * 16) * 2);
            #pragma unroll
            for (int g = 0; g < 2; g++)
                LDSM4(bl[2*g][0], bl[2*g][1], bl[2*g+1][0], bl[2*g+1][1],
                      bW_l + (uint32_t)(g * 16 * SW + k0) * 2);
            #pragma unroll
            for (int mf = 0; mf < 2; mf++)
                #pragma unroll
                for (int nf = 0; nf < 4; nf++) MMAF16(acc[mf][nf], ah[mf], whf[ks][nf]);
            #pragma unroll
            for (int mf = 0; mf < 2; mf++)
                #pragma unroll
                for (int nf = 0; nf < 4; nf++) MMAF16(acc[mf][nf], ah[mf], bl[nf]);
        }
        // ksteps 4..11: gather region (m-major, non-trans LDSM)
        #pragma unroll
        for (int ks = 4; ks < 12; ks++) {
            const int k0  = ks * 16;
            const int kp0 = k0 - 64;
            #pragma unroll
            for (int mf = 0; mf < 2; mf++)
                LDSM4(ah[mf][0], ah[mf][1], ah[mf][2], ah[mf][3],
                      aXG + (uint32_t)(mf * 16 * SXG + kp0) * 2);
            #pragma unroll
            for (int g = 0; g < 2; g++)
                LDSM4(bl[2*g][0], bl[2*g][1], bl[2*g+1][0], bl[2*g+1][1],
                      bW_l + (uint32_t)(g * 16 * SW + k0) * 2);
            #pragma unroll
            for (int mf = 0; mf < 2; mf++)
                #pragma unroll
                for (int nf = 0; nf < 4; nf++) MMAF16(acc[mf][nf], ah[mf], whf[ks][nf]);
            #pragma unroll
            for (int mf = 0; mf < 2; mf++)
                #pragma unroll
                for (int nf = 0; nf < 4; nf++) MMAF16(acc[mf][nf], ah[mf], bl[nf]);
        }

        // ---- epilogue: BN + ReLU + STG.64 ----
        {
            int tt = bid + i * GRID;
            int b  = tt >> 10;
            int m0 = (tt & 1023) << 6;
            const size_t obase = ((size_t)b * M_ + m0) * DOUT;
            #pragma unroll
            for (int nf = 0; nf < 4; nf++) {
                int d0 = wd * 32 + nf * 8 + 2 * tig;
                float s0 = sc_s[d0], s1 = sc_s[d0 + 1];
                float b0 = bi_s[d0], b1 = bi_s[d0 + 1];
                #pragma unroll
                for (int mf = 0; mf < 2; mf++) {
                    int rA = wm * 32 + mf * 16 + gid;
                    float2 v0, v1;
                    v0.x = fmaxf(fmaf(acc[mf][nf][0], s0, b0), 0.0f);
                    v0.y = fmaxf(fmaf(acc[mf][nf][1], s1, b1), 0.0f);
                    v1.x = fmaxf(fmaf(acc[mf][nf][2], s0, b0), 0.0f);
                    v1.y = fmaxf(fmaf(acc[mf][nf][3], s1, b1), 0.0f);
                    *(float2*)(out + obase + (size_t)rA * DOUT + d0)       = v0;
                    *(float2*)(out + obase + (size_t)(rA + 8) * DOUT + d0) = v1;
                }
            }
        }

        load_idx(i + 2, i & 1);
    }
}

// ---------------------------------------------------------------------------
extern "C" void kernel_launch(void* const* d_in, const int* in_sizes, int n_in,
                              void* d_out, int out_size) {
    const float* pre_x  = (const float*)d_in[0];
    const float* cur_x  = (const float*)d_in[1];
    const int*   up_idx = (const int*)d_in[2];
    const float* w      = (const float*)d_in[3];
    const float* bias   = (const float*)d_in[4];
    const float* gamma  = (const float*)d_in[5];
    const float* beta   = (const float*)d_in[6];
    const float* rmean  = (const float*)d_in[7];
    const float* rvar   = (const float*)d_in[8];
    float*       out    = (float*)d_out;

    dim3 tg(N_ / 32, CCUR / 32, B_);
    transpose_split_kernel<<<tg, dim3(32, 8)>>>(cur_x);
    presplit_kernel<<<(int)(((size_t)B_ * CPRE * M_ / 2 + 255) / 256), 256>>>(pre_x);
    wsplit_kernel<<<48, 256>>>(w);

    cudaFuncSetAttribute(fused_kernel, cudaFuncAttributeMaxDynamicSharedMemorySize, SM_TOT);
    fused_kernel<<<GRID, THREADS, SM_TOT>>>(up_idx, bias, gamma, beta,
                                            rmean, rvar, out);
}

// round 15
// speedup vs baseline: 1.8893x; 1.1901x over previous
#include <cuda_runtime.h>
#include <cuda_fp16.h>
#include <cstdint>

// Problem constants
constexpr int B_   = 4;
constexpr int M_   = 65536;
constexpr int N_   = 16384;
constexpr int CPRE = 64;
constexpr int CCUR = 128;
constexpr int CIN  = 192;
constexpr int DOUT = 128;

constexpr int MT      = 128;     // m-tile (persistent, double-buffered)
constexpr int THREADS = 512;     // 16 warps -> 4 per SMSP
constexpr int GRID    = 148;     // persistent: 1 CTA/SM
constexpr int NTILES  = (M_ / MT) * B_;   // 2048

// SMEM strides (fp16 elems; word stride ≡ 4 mod 8 -> conflict-free LDSM)
constexpr int SXA = 136;   // pre_x tile, k-major: [64 k][128 m + pad]
constexpr int SXG = 136;   // gather tile, m-major: [128 m][128 k' + pad]
constexpr int SW  = 200;   // w tile, d-major: [128 d][192 k + pad]

constexpr int XA_BYTES = 64 * SXA * 2;     // 17408
constexpr int XG_BYTES = 128 * SXG * 2;    // 34816
constexpr int BUF_XA   = 0;
constexpr int BUF_XG   = XA_BYTES;
constexpr int BUF_SZ   = XA_BYTES + XG_BYTES;   // 52224

constexpr int SM_IDX  = 0;          // 2 x 128 int
constexpr int SM_SC   = 1024;
constexpr int SM_BI   = 1536;
constexpr int SM_BUF0 = 2048;
constexpr int SM_BUF1 = SM_BUF0 + BUF_SZ;       // 54272
constexpr int SM_W    = SM_BUF1 + BUF_SZ;       // 106496
constexpr int SM_TOT  = SM_W + 128 * SW * 2;    // 157696 (~154 KB)

// Pre-converted fp16 scratch (single-pass fp16 GEMM; error budget validated)
__device__ __half   g_curT[(size_t)B_ * N_ * CCUR];   // (B,N,C) 16 MiB
__device__ __half   g_pre[(size_t)B_ * CPRE * M_];    // (B,C,M) 32 MiB
__device__ uint32_t g_w[128 * (SW / 2)];              // W smem image [d][k/2]

// ---------------------------------------------------------------------------
__device__ __forceinline__ uint32_t pk2h(float a, float b) {
    __half2 t = __floats2half2_rn(a, b);
    return *(uint32_t*)&t;
}

// Transpose + fp16-convert cur_x (B,C,N) -> (B,N,C)
__global__ void transpose_split_kernel(const float* __restrict__ cur) {
    __shared__ float t[32][33];
    int b  = blockIdx.z;
    int c0 = blockIdx.y * 32;
    int n0 = blockIdx.x * 32;
    const float* src = cur + (size_t)b * CCUR * N_;
    #pragma unroll
    for (int r = threadIdx.y; r < 32; r += 8)
        t[r][threadIdx.x] = src[(size_t)(c0 + r) * N_ + n0 + threadIdx.x];
    __syncthreads();
    size_t dbase = (size_t)b * N_ * CCUR;
    #pragma unroll
    for (int r = threadIdx.y; r < 32; r += 8)
        g_curT[dbase + (size_t)(n0 + r) * CCUR + c0 + threadIdx.x] =
            __float2half_rn(t[threadIdx.x][r]);
}

// Elementwise fp16-convert pre_x (pair-packed stores)
__global__ void presplit_kernel(const float* __restrict__ pre) {
    size_t i = (size_t)blockIdx.x * blockDim.x + threadIdx.x;   // pair index
    if (i >= (size_t)B_ * CPRE * M_ / 2) return;
    float2 v = ((const float2*)pre)[i];
    ((uint32_t*)g_pre)[i] = pk2h(v.x, v.y);
}

// W -> fp16 smem image [d][k] (pair-packed along k)
__global__ void wsplit_kernel(const float* __restrict__ w) {
    int i = blockIdx.x * 256 + threadIdx.x;   // 128 d x 96 k-pairs
    if (i >= DOUT * (CIN / 2)) return;
    int d = i & 127, kp = i >> 7;
    g_w[d * (SW / 2) + kp] =
        pk2h(w[(size_t)(2 * kp) * DOUT + d], w[(size_t)(2 * kp + 1) * DOUT + d]);
}

// ---------------------------------------------------------------------------
__device__ __forceinline__ uint32_t smem_u32(const void* p) {
    uint32_t a;
    asm("{ .reg .u64 t; cvta.to.shared.u64 t, %1; cvt.u32.u64 %0, t; }" : "=r"(a) : "l"(p));
    return a;
}
__device__ __forceinline__ void cp_async16(uint32_t dst, const void* src) {
    asm volatile("cp.async.cg.shared.global [%0], [%1], 16;" :: "r"(dst), "l"(src));
}

#define LDSM4(r0, r1, r2, r3, addr)                                          \
    asm volatile("ldmatrix.sync.aligned.m8n8.x4.shared.b16 {%0,%1,%2,%3}, [%4];" \
                 : "=r"(r0), "=r"(r1), "=r"(r2), "=r"(r3) : "r"(addr))
#define LDSM4T(r0, r1, r2, r3, addr)                                         \
    asm volatile("ldmatrix.sync.aligned.m8n8.x4.trans.shared.b16 {%0,%1,%2,%3}, [%4];" \
                 : "=r"(r0), "=r"(r1), "=r"(r2), "=r"(r3) : "r"(addr))
#define MMAF16(c, a, b)                                                      \
    asm volatile("mma.sync.aligned.m16n8k16.row.col.f32.f16.f16.f32 "         \
                 "{%0,%1,%2,%3}, {%4,%5,%6,%7}, {%8,%9}, {%0,%1,%2,%3};"      \
                 : "+f"((c)[0]), "+f"((c)[1]), "+f"((c)[2]), "+f"((c)[3])     \
                 : "r"((a)[0]), "r"((a)[1]), "r"((a)[2]), "r"((a)[3]),        \
                   "r"((b)[0]), "r"((b)[1]))

extern __shared__ char smc[];

__global__ __launch_bounds__(THREADS, 1)
void fused_kernel(const int* __restrict__ up_idx,
                  const float* __restrict__ bias,
                  const float* __restrict__ gamma,
                  const float* __restrict__ beta,
                  const float* __restrict__ rmean,
                  const float* __restrict__ rvar,
                  float* __restrict__ out) {
    const int bid  = blockIdx.x;
    const int tid  = threadIdx.x;
    const int wid  = tid >> 5;
    const int lane = tid & 31;

    int*   idx_s = (int*)(smc + SM_IDX);     // [2][128]
    float* sc_s  = (float*)(smc + SM_SC);
    float* bi_s  = (float*)(smc + SM_BI);
    const uint32_t base_u32 = smem_u32(smc);

    const int nt = (NTILES - 1 - bid) / GRID + 1;

    auto load_idx = [&](int i_local, int slot) {
        int tt = bid + i_local * GRID;
        if (tid < MT && i_local < nt) {
            int b  = tt >> 9;
            int m0 = (tt & 511) << 7;
            idx_s[slot * MT + tid] = up_idx[(size_t)b * M_ + m0 + tid] & (N_ - 1);
        }
    };

    auto stage_X = [&](int i_local, int bufp) {
        int tt = bid + i_local * GRID;
        int b  = tt >> 9;
        int m0 = (tt & 511) << 7;
        uint32_t bb = base_u32 + (bufp ? SM_BUF1 : SM_BUF0);
        // XA: 64 k-rows x 256B (128 m fp16)
        {
            const char* s = (const char*)(g_pre + (size_t)b * CPRE * M_ + m0);
            #pragma unroll
            for (int i = tid; i < 64 * 16; i += THREADS) {
                int k = i >> 4, c = i & 15;
                cp_async16(bb + BUF_XA + (uint32_t)(k * (SXA * 2) + c * 16),
                           s + (size_t)k * M_ * 2 + c * 16);
            }
        }
        // XG: 128 gathered rows x 256B
        {
            const char* s = (const char*)(g_curT + (size_t)b * N_ * CCUR);
            const int* idxp = idx_s + (i_local & 1) * MT;
            #pragma unroll
            for (int i = tid; i < 128 * 16; i += THREADS) {
                int m = i >> 4, c = i & 15;
                cp_async16(bb + BUF_XG + (uint32_t)(m * (SXG * 2) + c * 16),
                           s + (size_t)idxp[m] * (CCUR * 2) + c * 16);
            }
        }
    };

    // ---- prologue ----
    if (tid < DOUT) {
        float s = gamma[tid] * rsqrtf(rvar[tid] + 1e-5f);
        sc_s[tid] = s;
        bi_s[tid] = (bias[tid] - rmean[tid]) * s + beta[tid];
    }
    load_idx(0, 0);
    __syncthreads();

    // G0: W (once per CTA)
    {
        const char* s = (const char*)g_w;
        for (int i = tid; i < 128 * SW * 2 / 16; i += THREADS)
            cp_async16(base_u32 + SM_W + 16 * i, s + 16 * i);
        asm volatile("cp.async.commit_group;");
    }
    // G1: tile 0
    stage_X(0, 0);
    asm volatile("cp.async.commit_group;");
    load_idx(1, 1);

    // per-lane ldmatrix addressing
    const int wm = wid & 3;    // m-quarter (32 m)
    const int wd = wid >> 2;   // d-quarter (32 d)
    const int r  = lane & 7;
    const int q  = lane >> 3;
    const uint32_t oA = (uint32_t)((r + ((q >= 2) ? 8 : 0)) * SXA +
                                   wm * 32 + ((q & 1) ? 8 : 0)) * 2;
    const uint32_t oG = (uint32_t)((wm * 32 + r + ((q & 1) ? 8 : 0)) * SXG +
                                   ((q >= 2) ? 8 : 0)) * 2;
    const uint32_t bW = base_u32 + SM_W +
                        (uint32_t)((wd * 32 + r + ((q >= 2) ? 8 : 0)) * SW +
                                   ((q & 1) ? 8 : 0)) * 2;

    const int gid = lane >> 2;
    const int tig = lane & 3;

    // ---- persistent tile loop ----
    for (int i = 0; i < nt; i++) {
        __syncthreads();                         // buf (i+1)&1 free; idx slot visible
        if (i + 1 < nt) stage_X(i + 1, (i + 1) & 1);
        asm volatile("cp.async.commit_group;");
        asm volatile("cp.async.wait_group 1;" ::: "memory");   // tile i (and W) done
        __syncthreads();

        const uint32_t bb  = base_u32 + ((i & 1) ? SM_BUF1 : SM_BUF0);
        const uint32_t aXA = bb + BUF_XA + oA;
        const uint32_t aXG = bb + BUF_XG + oG;

        float acc[2][4][4];
        #pragma unroll
        for (int mf = 0; mf < 2; mf++)
            #pragma unroll
            for (int j = 0; j < 4; j++)
                #pragma unroll
                for (int e = 0; e < 4; e++) acc[mf][j][e] = 0.0f;

        uint32_t ah[2][4], bh[4][2];

        // ksteps 0..3: pre_x region (k-major, trans LDSM)
        #pragma unroll
        for (int ks = 0; ks < 4; ks++) {
            const int k0 = ks * 16;
            #pragma unroll
            for (int mf = 0; mf < 2; mf++)
                LDSM4T(ah[mf][0], ah[mf][1], ah[mf][2], ah[mf][3],
                       aXA + (uint32_t)(k0 * SXA + mf * 16) * 2);
            #pragma unroll
            for (int g = 0; g < 2; g++)
                LDSM4(bh[2*g][0], bh[2*g][1], bh[2*g+1][0], bh[2*g+1][1],
                      bW + (uint32_t)(g * 16 * SW + k0) * 2);
            #pragma unroll
            for (int mf = 0; mf < 2; mf++)
                #pragma unroll
                for (int nf = 0; nf < 4; nf++) MMAF16(acc[mf][nf], ah[mf], bh[nf]);
        }
        // ksteps 4..11: gather region (m-major, non-trans LDSM)
        #pragma unroll
        for (int ks = 4; ks < 12; ks++) {
            const int k0  = ks * 16;
            const int kp0 = k0 - 64;
            #pragma unroll
            for (int mf = 0; mf < 2; mf++)
                LDSM4(ah[mf][0], ah[mf][1], ah[mf][2], ah[mf][3],
                      aXG + (uint32_t)(mf * 16 * SXG + kp0) * 2);
            #pragma unroll
            for (int g = 0; g < 2; g++)
                LDSM4(bh[2*g][0], bh[2*g][1], bh[2*g+1][0], bh[2*g+1][1],
                      bW + (uint32_t)(g * 16 * SW + k0) * 2);
            #pragma unroll
            for (int mf = 0; mf < 2; mf++)
                #pragma unroll
                for (int nf = 0; nf < 4; nf++) MMAF16(acc[mf][nf], ah[mf], bh[nf]);
        }

        // ---- epilogue: BN + ReLU + STG.64 ----
        {
            int tt = bid + i * GRID;
            int b  = tt >> 9;
            int m0 = (tt & 511) << 7;
            const size_t obase = ((size_t)b * M_ + m0) * DOUT;
            #pragma unroll
            for (int nf = 0; nf < 4; nf++) {
                int d0 = wd * 32 + nf * 8 + 2 * tig;
                float s0 = sc_s[d0], s1 = sc_s[d0 + 1];
                float b0 = bi_s[d0], b1 = bi_s[d0 + 1];
                #pragma unroll
                for (int mf = 0; mf < 2; mf++) {
                    int rA = wm * 32 + mf * 16 + gid;
                    float2 v0, v1;
                    v0.x = fmaxf(fmaf(acc[mf][nf][0], s0, b0), 0.0f);
                    v0.y = fmaxf(fmaf(acc[mf][nf][1], s1, b1), 0.0f);
                    v1.x = fmaxf(fmaf(acc[mf][nf][2], s0, b0), 0.0f);
                    v1.y = fmaxf(fmaf(acc[mf][nf][3], s1, b1), 0.0f);
                    *(float2*)(out + obase + (size_t)rA * DOUT + d0)       = v0;
                    *(float2*)(out + obase + (size_t)(rA + 8) * DOUT + d0) = v1;
                }
            }
        }

        load_idx(i + 2, i & 1);
    }
}

// ---------------------------------------------------------------------------
extern "C" void kernel_launch(void* const* d_in, const int* in_sizes, int n_in,
                              void* d_out, int out_size) {
    const float* pre_x  = (const float*)d_in[0];
    const float* cur_x  = (const float*)d_in[1];
    const int*   up_idx = (const int*)d_in[2];
    const float* w      = (const float*)d_in[3];
    const float* bias   = (const float*)d_in[4];
    const float* gamma  = (const float*)d_in[5];
    const float* beta   = (const float*)d_in[6];
    const float* rmean  = (const float*)d_in[7];
    const float* rvar   = (const float*)d_in[8];
    float*       out    = (float*)d_out;

    dim3 tg(N_ / 32, CCUR / 32, B_);
    transpose_split_kernel<<<tg, dim3(32, 8)>>>(cur_x);
    presplit_kernel<<<(int)(((size_t)B_ * CPRE * M_ / 2 + 255) / 256), 256>>>(pre_x);
    wsplit_kernel<<<48, 256>>>(w);

    cudaFuncSetAttribute(fused_kernel, cudaFuncAttributeMaxDynamicSharedMemorySize, SM_TOT);
    fused_kernel<<<GRID, THREADS, SM_TOT>>>(up_idx, bias, gamma, beta,
                                            rmean, rvar, out);
}